// round 3
// baseline (speedup 1.0000x reference)
#include <cuda_runtime.h>
#include <cstdint>

// Problem constants
static constexpr int NB = 16;    // batch
static constexpr int NC = 256;   // channels
static constexpr int NH = 64;
static constexpr int NW = 64;
static constexpr int NP = 9;     // patch (2*4+1)
static constexpr int DISP = 4;

// Tiling
static constexpr int TI = 4;             // i-rows per block
static constexpr int CH = 4;             // channels per pipeline stage
static constexpr int NSTAGE = NC / CH;   // 64
static constexpr int YROWS = TI + 2 * DISP;  // 12
static constexpr int PITCH = 384;        // bytes per smem row (multiple of 128)
static constexpr int XAREA = CH * TI * PITCH;      // 6144
static constexpr int YAREA = CH * YROWS * PITCH;   // 18432
static constexpr int BUFBYTES = XAREA + YAREA;     // 24576
static constexpr int NTHREADS = 288;     // 9 warps: warp w -> di = w
static constexpr int NBUF = 4;
static constexpr int NSLOT = CH * YROWS + CH * TI;   // 48 y-rows + 16 x-rows = 64
static constexpr int ROWBYTES = NW * 4;              // 256B per bulk copy
static constexpr int STAGE_BYTES = CH * NH * NW * 4; // 65536 (4-channel advance)

// smem map: [0..8*NBUF*8) mbarriers (full[4], empty[4]); buffers at +128
static constexpr int MBAR_FULL = 0;      // full[b] at  b*8
static constexpr int MBAR_EMPTY = 32;    // empty[b] at 32 + b*8
static constexpr int BUF0 = 128;
static constexpr int SMEM_TOTAL = BUF0 + NBUF * BUFBYTES;  // 98432

__device__ __forceinline__ unsigned skew(int r) {
    return ((r & 1) << 4) + ((r & 2) << 5);
}
__device__ __forceinline__ unsigned long long pk(float lo, float hi) {
    unsigned long long r;
    asm("mov.b64 %0, {%1, %2};" : "=l"(r) : "f"(lo), "f"(hi));
    return r;
}
__device__ __forceinline__ void upk(unsigned long long v, float& lo, float& hi) {
    asm("mov.b64 {%0, %1}, %2;" : "=f"(lo), "=f"(hi) : "l"(v));
}
// Packed dual fp32 FMA (Blackwell): 2x FFMA throughput vs scalar FFMA.
__device__ __forceinline__ void fma2(unsigned long long& acc,
                                     unsigned long long a, unsigned long long b) {
    asm("fma.rn.f32x2 %0, %1, %2, %0;" : "+l"(acc) : "l"(a), "l"(b));
}

__device__ __forceinline__ void mbar_init(unsigned addr, unsigned count) {
    asm volatile("mbarrier.init.shared.b64 [%0], %1;" :: "r"(addr), "r"(count) : "memory");
}
__device__ __forceinline__ void mbar_arrive(unsigned addr) {
    asm volatile("mbarrier.arrive.shared.b64 _, [%0];" :: "r"(addr) : "memory");
}
__device__ __forceinline__ void mbar_arrive_expect(unsigned addr, unsigned bytes) {
    asm volatile("mbarrier.arrive.expect_tx.shared.b64 _, [%0], %1;"
                 :: "r"(addr), "r"(bytes) : "memory");
}
__device__ __forceinline__ void mbar_wait(unsigned addr, unsigned parity) {
    asm volatile(
        "{\n\t"
        ".reg .pred P;\n\t"
        "WL_%=:\n\t"
        "mbarrier.try_wait.parity.acquire.cta.shared::cta.b64 P, [%0], %1, 0x989680;\n\t"
        "@P bra.uni WD_%=;\n\t"
        "bra.uni WL_%=;\n\t"
        "WD_%=:\n\t"
        "}"
        :: "r"(addr), "r"(parity) : "memory");
}
__device__ __forceinline__ void bulk_g2s(unsigned dst, const void* src,
                                         unsigned bytes, unsigned mbar) {
    asm volatile(
        "cp.async.bulk.shared::cta.global.mbarrier::complete_tx::bytes "
        "[%0], [%1], %2, [%3];"
        :: "r"(dst), "l"(src), "r"(bytes), "r"(mbar) : "memory");
}

__global__ void __launch_bounds__(NTHREADS, 2)
corr_kernel(const float* __restrict__ x, const float* __restrict__ y,
            float* __restrict__ out) {
    extern __shared__ char smem[];

    const int tid = threadIdx.x;
    const int di  = tid >> 5;        // 0..8, one displacement-row per warp
    const int lane = tid & 31;
    const int jg  = lane >> 2;       // 0..7 : group of 8 output columns
    const int ti  = lane & 3;        // 0..3 : i-row inside tile
    const int i0  = blockIdx.x * TI;
    const int b   = blockIdx.y;

    unsigned smem_u32;
    asm("{ .reg .u64 t; cvta.to.shared.u64 t, %1; cvt.u32.u64 %0, t; }"
        : "=r"(smem_u32) : "l"(smem));

    // Zero all buffers once: halo columns / out-of-range rows stay zero forever.
    for (int o = tid * 16; o < NBUF * BUFBYTES; o += NTHREADS * 16)
        *reinterpret_cast<float4*>(smem + BUF0 + o) = make_float4(0.f, 0.f, 0.f, 0.f);

    if (tid == 0) {
#pragma unroll
        for (int bb = 0; bb < NBUF; ++bb) {
            mbar_init(smem_u32 + MBAR_FULL + bb * 8, NSLOT);     // 64 owner arrivals
            mbar_init(smem_u32 + MBAR_EMPTY + bb * 8, NTHREADS); // all threads arrive
        }
    }
    __syncthreads();
    // Order the generic-proxy zero-stores before async-proxy TMA writes.
    asm volatile("fence.proxy.async.shared::cta;" ::: "memory");

    // ---- owner slot precompute (stage-invariant) ----
    // Owner tids 0,4,8,...,252 own slot k = tid>>2.
    const bool is_owner = ((tid & 3) == 0) && ((tid >> 2) < NSLOT);
    const char* src0 = nullptr;  // stage-0 source (advances by STAGE_BYTES)
    int dst_off = 0;             // offset within a buffer
    bool valid = false;
    if (is_owner) {
        const int k = tid >> 2;
        if (k < CH * YROWS) {                    // y slot
            const int cc = k / YROWS;
            const int rr = k % YROWS;
            const int gy = i0 - DISP + rr;
            valid = ((unsigned)gy < (unsigned)NH);
            if (valid)
                src0 = reinterpret_cast<const char*>(
                    y + (((size_t)(b * NC + cc) * NH + gy) * NW));
            dst_off = XAREA + cc * (YROWS * PITCH) + rr * PITCH + (int)skew(rr) + 16;
        } else {                                 // x slot
            const int j  = k - CH * YROWS;
            const int cc = j >> 2;
            const int rr = j & 3;
            valid = true;
            src0 = reinterpret_cast<const char*>(
                x + (((size_t)(b * NC + cc) * NH + (i0 + rr)) * NW));
            dst_off = cc * (TI * PITCH) + rr * PITCH + (int)skew(rr);
        }
    }

    // ---- prologue: fill the pipeline (stages 0..NBUF-1) ----
    if (is_owner) {
#pragma unroll
        for (int t = 0; t < NBUF; ++t) {
            const unsigned fb = smem_u32 + MBAR_FULL + (t & (NBUF - 1)) * 8;
            if (valid) {
                mbar_arrive_expect(fb, ROWBYTES);
                bulk_g2s(smem_u32 + BUF0 + (t & (NBUF - 1)) * BUFBYTES + dst_off,
                         src0 + (size_t)t * STAGE_BYTES, ROWBYTES, fb);
            } else {
                mbar_arrive(fb);
            }
        }
    }

    unsigned long long acc[NP][4];
#pragma unroll
    for (int d = 0; d < NP; ++d)
#pragma unroll
        for (int m = 0; m < 4; ++m) acc[d][m] = 0ull;

    const int r = ti + di;  // y smem row for this thread (0..11)
    const unsigned xoff = (unsigned)BUF0 + (unsigned)(ti * PITCH) + skew(ti) + jg * 32;
    const unsigned yoff = (unsigned)BUF0 + (unsigned)XAREA
                        + (unsigned)(r * PITCH) + skew(r) + jg * 32;

    for (int s = 0; s < NSTAGE; ++s) {
        const int bb = s & (NBUF - 1);
        const unsigned parity = (s >> 2) & 1;

        mbar_wait(smem_u32 + MBAR_FULL + bb * 8, parity);

        const char* base = smem + bb * BUFBYTES;
#pragma unroll
        for (int cc = 0; cc < CH; ++cc) {
            const char* xp = base + cc * (TI * PITCH) + xoff;
            const char* yp = base + cc * (YROWS * PITCH) + yoff;

            const float4 xa = *reinterpret_cast<const float4*>(xp);
            const float4 xb = *reinterpret_cast<const float4*>(xp + 16);
            const float4 y0 = *reinterpret_cast<const float4*>(yp);
            const float4 y1 = *reinterpret_cast<const float4*>(yp + 16);
            const float4 y2 = *reinterpret_cast<const float4*>(yp + 32);
            const float4 y3 = *reinterpret_cast<const float4*>(yp + 48);

            unsigned long long X[4] = {pk(xa.x, xa.y), pk(xa.z, xa.w),
                                       pk(xb.x, xb.y), pk(xb.z, xb.w)};
            const float w[16] = {y0.x, y0.y, y0.z, y0.w, y1.x, y1.y, y1.z, y1.w,
                                 y2.x, y2.y, y2.z, y2.w, y3.x, y3.y, y3.z, y3.w};

            unsigned long long Wp[8], Sp[7];
#pragma unroll
            for (int q = 0; q < 8; ++q) Wp[q] = pk(w[2 * q], w[2 * q + 1]);
#pragma unroll
            for (int q = 0; q < 7; ++q) Sp[q] = pk(w[2 * q + 1], w[2 * q + 2]);

#pragma unroll
            for (int dj = 0; dj < NP; ++dj) {
                const int e = dj >> 1;
#pragma unroll
                for (int m = 0; m < 4; ++m) {
                    const unsigned long long yv = (dj & 1) ? Sp[m + e] : Wp[m + e];
                    fma2(acc[dj][m], X[m], yv);
                }
            }
        }

        // Consumed buffer bb for stage s.
        mbar_arrive(smem_u32 + MBAR_EMPTY + bb * 8);

        // Owner re-issues its slot for stage s+NBUF into the same buffer.
        const int t = s + NBUF;
        if (is_owner && t < NSTAGE) {
            mbar_wait(smem_u32 + MBAR_EMPTY + bb * 8, parity);
            const unsigned fb = smem_u32 + MBAR_FULL + bb * 8;
            if (valid) {
                mbar_arrive_expect(fb, ROWBYTES);
                bulk_g2s(smem_u32 + BUF0 + bb * BUFBYTES + dst_off,
                         src0 + (size_t)t * STAGE_BYTES, ROWBYTES, fb);
            } else {
                mbar_arrive(fb);
            }
        }
    }

    // ---- epilogue: scale by 1/C and store ----
    const float sc = 1.0f / (float)NC;
    float* obase = out + (((size_t)b * (NP * NP) + (size_t)di * NP) * NH + (i0 + ti)) * NW
                       + jg * 8;
#pragma unroll
    for (int dj = 0; dj < NP; ++dj) {
        float4 o;
        upk(acc[dj][0], o.x, o.y);
        upk(acc[dj][1], o.z, o.w);
        o.x *= sc; o.y *= sc; o.z *= sc; o.w *= sc;
        *reinterpret_cast<float4*>(obase + (size_t)dj * NH * NW) = o;
        upk(acc[dj][2], o.x, o.y);
        upk(acc[dj][3], o.z, o.w);
        o.x *= sc; o.y *= sc; o.z *= sc; o.w *= sc;
        *reinterpret_cast<float4*>(obase + (size_t)dj * NH * NW + 4) = o;
    }
}

extern "C" void kernel_launch(void* const* d_in, const int* in_sizes, int n_in,
                              void* d_out, int out_size) {
    const float* x = (const float*)d_in[0];
    const float* y = (const float*)d_in[1];
    float* out = (float*)d_out;
    (void)in_sizes; (void)n_in; (void)out_size;

    cudaFuncSetAttribute(corr_kernel,
                         cudaFuncAttributeMaxDynamicSharedMemorySize, SMEM_TOTAL);

    dim3 grid(NH / TI, NB);   // (16, 16) = 256 blocks
    corr_kernel<<<grid, NTHREADS, SMEM_TOTAL>>>(x, y, out);
}

// round 4
// speedup vs baseline: 1.2301x; 1.2301x over previous
#include <cuda_runtime.h>
#include <cstdint>

// Problem constants
static constexpr int NB = 16;    // batch
static constexpr int NC = 256;   // channels
static constexpr int NH = 64;
static constexpr int NW = 64;
static constexpr int NP = 9;     // patch (2*4+1)
static constexpr int DISP = 4;

// Tiling
static constexpr int TI = 4;             // i-rows per block
static constexpr int CH = 8;             // channels per pipeline stage
static constexpr int NSTAGE = NC / CH;   // 32
static constexpr int YROWS = TI + 2 * DISP;  // 12
static constexpr int PITCH = 384;        // bytes per smem row (multiple of 128)
static constexpr int XAREA = CH * TI * PITCH;      // 12288
static constexpr int YAREA = CH * YROWS * PITCH;   // 36864
static constexpr int BUFBYTES = XAREA + YAREA;     // 49152
static constexpr int NTHREADS = 288;     // 9 warps: warp w -> di = w
static constexpr int NROWS = CH * YROWS + CH * TI; // 96 y-rows + 32 x-rows = 128
static constexpr int STAGE_BYTES = CH * NH * NW * 4;  // 131072

__device__ __forceinline__ unsigned skew(int r) {
    return ((r & 1) << 4) + ((r & 2) << 5);
}
__device__ __forceinline__ void upk(unsigned long long v, float& lo, float& hi) {
    asm("mov.b64 {%0, %1}, %2;" : "=f"(lo), "=f"(hi) : "l"(v));
}
__device__ __forceinline__ unsigned long long pk(float lo, float hi) {
    unsigned long long r;
    asm("mov.b64 %0, {%1, %2};" : "=l"(r) : "f"(lo), "f"(hi));
    return r;
}
// Packed dual fp32 FMA (Blackwell): 2x FFMA throughput vs scalar FFMA.
__device__ __forceinline__ void fma2(unsigned long long& acc,
                                     unsigned long long a, unsigned long long b) {
    asm("fma.rn.f32x2 %0, %1, %2, %0;" : "+l"(acc) : "l"(a), "l"(b));
}
// 16B shared load directly into two aligned u64 pairs (no pack MOVs).
__device__ __forceinline__ void lds2(unsigned addr,
                                     unsigned long long& a, unsigned long long& b) {
    asm volatile("ld.shared.v2.b64 {%0, %1}, [%2];"
                 : "=l"(a), "=l"(b) : "r"(addr));
}
__device__ __forceinline__ void cpa16(unsigned dst, const void* src) {
    asm volatile("cp.async.cg.shared.global [%0], [%1], 16;"
                 :: "r"(dst), "l"(src) : "memory");
}

__global__ void __launch_bounds__(NTHREADS, 2)
corr_kernel(const float* __restrict__ x, const float* __restrict__ y,
            float* __restrict__ out) {
    extern __shared__ char smem[];

    const int tid = threadIdx.x;
    const int di  = tid >> 5;        // 0..8, one displacement-row per warp
    const int lane = tid & 31;
    const int jg  = lane >> 2;       // 0..7 : group of 8 output columns
    const int ti  = lane & 3;        // 0..3 : i-row inside tile
    const int i0  = blockIdx.x * TI;
    const int b   = blockIdx.y;

    unsigned smem_u32;
    asm("{ .reg .u64 t; cvta.to.shared.u64 t, %1; cvt.u32.u64 %0, t; }"
        : "=r"(smem_u32) : "l"(smem));

    // Zero both buffers once: halo columns / out-of-range rows stay zero forever.
    for (int o = tid * 16; o < 2 * BUFBYTES; o += NTHREADS * 16)
        *reinterpret_cast<float4*>(smem + o) = make_float4(0.f, 0.f, 0.f, 0.f);

    // ---- loader: 256 threads, one 128B row-half each (stage-invariant) ----
    // row = tid>>1 (0..127), half = tid&1. Rows 0..95 = y, 96..127 = x.
    const bool ldr = (tid < 2 * NROWS);
    const char* src0 = reinterpret_cast<const char*>(x);
    unsigned dsto = 0;
    bool valid = false;
    if (ldr) {
        const int row = tid >> 1, half = tid & 1;
        if (row < CH * YROWS) {
            const int cc = row / YROWS;
            const int rr = row % YROWS;
            const int gy = i0 - DISP + rr;
            valid = ((unsigned)gy < (unsigned)NH);
            if (valid)
                src0 = reinterpret_cast<const char*>(
                    y + (((size_t)(b * NC + cc) * NH + gy) * NW + half * 32));
            dsto = XAREA + cc * (YROWS * PITCH) + rr * PITCH + skew(rr)
                   + 16 + half * 128;
        } else {
            const int j  = row - CH * YROWS;
            const int cc = j >> 2;
            const int rr = j & 3;
            valid = true;
            src0 = reinterpret_cast<const char*>(
                x + (((size_t)(b * NC + cc) * NH + (i0 + rr)) * NW + half * 32));
            dsto = cc * (TI * PITCH) + rr * PITCH + skew(rr) + half * 128;
        }
    }
    __syncthreads();   // zero-fill complete before first cp.async

    auto issue = [&](int stage) {
        if (valid) {
            const char* s = src0 + (size_t)stage * STAGE_BYTES;
            const unsigned d = smem_u32 + (unsigned)((stage & 1) * BUFBYTES) + dsto;
#pragma unroll
            for (int k = 0; k < 8; ++k) cpa16(d + k * 16, s + k * 16);
        }
        asm volatile("cp.async.commit_group;" ::: "memory");
    };

    issue(0);

    // Accumulators: even dj -> 4 aligned col-pairs; odd dj -> 3 mid pairs + 2 scalars.
    unsigned long long accE[5][4], accO[4][3];
    float sA[4], sB[4];
#pragma unroll
    for (int e = 0; e < 5; ++e)
#pragma unroll
        for (int m = 0; m < 4; ++m) accE[e][m] = 0ull;
#pragma unroll
    for (int o = 0; o < 4; ++o) {
#pragma unroll
        for (int m = 0; m < 3; ++m) accO[o][m] = 0ull;
        sA[o] = 0.f; sB[o] = 0.f;
    }

    const int r = ti + di;  // y smem row for this thread (0..11)
    const unsigned xoff = smem_u32 + (unsigned)(ti * PITCH) + skew(ti) + jg * 32;
    const unsigned yoff = smem_u32 + (unsigned)XAREA
                        + (unsigned)(r * PITCH) + skew(r) + jg * 32;

    for (int s = 0; s < NSTAGE; ++s) {
        // Wait for this stage's data (own group), publish via barrier, then
        // prefetch the next stage into the buffer everyone just finished reading.
        asm volatile("cp.async.wait_group 0;" ::: "memory");
        __syncthreads();
        if (s + 1 < NSTAGE) issue(s + 1);

        const unsigned boff = (unsigned)((s & 1) * BUFBYTES);
#pragma unroll 2
        for (int cc = 0; cc < CH; ++cc) {
            const unsigned xp = boff + (unsigned)(cc * (TI * PITCH)) + xoff;
            const unsigned yp = boff + (unsigned)(cc * (YROWS * PITCH)) + yoff;

            unsigned long long X[4], W[8];
            lds2(xp,      X[0], X[1]);
            lds2(xp + 16, X[2], X[3]);
            lds2(yp,      W[0], W[1]);
            lds2(yp + 16, W[2], W[3]);
            lds2(yp + 32, W[4], W[5]);
            lds2(yp + 48, W[6], W[7]);

            // Scalar views (register aliases; mov.b64 unpacks are coalesced).
            float x0, x1, x2, x3, x4, x5, x6, x7;
            upk(X[0], x0, x1); upk(X[1], x2, x3);
            upk(X[2], x4, x5); upk(X[3], x6, x7);

            // Shifted x pairs for odd displacements (only 3 packs per channel).
            unsigned long long Sx[3] = {pk(x1, x2), pk(x3, x4), pk(x5, x6)};

            // Even dj: aligned x-pairs times aligned y-pairs.
#pragma unroll
            for (int e = 0; e < 5; ++e)
#pragma unroll
                for (int m = 0; m < 4; ++m)
                    fma2(accE[e][m], X[m], W[m + e]);

            // Odd dj: shifted x-pairs times aligned y-pairs + scalar borders.
#pragma unroll
            for (int o = 0; o < 4; ++o) {
#pragma unroll
                for (int m = 0; m < 3; ++m)
                    fma2(accO[o][m], Sx[m], W[m + 1 + o]);
                float wl, wh, vl, vh;
                upk(W[o], wl, wh);       // wh = w[2o+1] = w[dj]
                upk(W[4 + o], vl, vh);   // vl = w[8+2o] = w[7+dj]
                sA[o] = fmaf(x0, wh, sA[o]);
                sB[o] = fmaf(x7, vl, sB[o]);
            }
        }
    }

    // ---- epilogue: scale by 1/C and store ----
    const float sc = 1.0f / (float)NC;
    float* obase = out + (((size_t)b * (NP * NP) + (size_t)di * NP) * NH + (i0 + ti)) * NW
                       + jg * 8;
#pragma unroll
    for (int e = 0; e < 5; ++e) {          // dj = 2e
        float* op = obase + (size_t)(2 * e) * NH * NW;
        float4 v;
        upk(accE[e][0], v.x, v.y); upk(accE[e][1], v.z, v.w);
        v.x *= sc; v.y *= sc; v.z *= sc; v.w *= sc;
        *reinterpret_cast<float4*>(op) = v;
        upk(accE[e][2], v.x, v.y); upk(accE[e][3], v.z, v.w);
        v.x *= sc; v.y *= sc; v.z *= sc; v.w *= sc;
        *reinterpret_cast<float4*>(op + 4) = v;
    }
#pragma unroll
    for (int o = 0; o < 4; ++o) {          // dj = 2o+1
        float* op = obase + (size_t)(2 * o + 1) * NH * NW;
        float f1, f2, f3, f4, f5, f6;
        upk(accO[o][0], f1, f2);
        upk(accO[o][1], f3, f4);
        upk(accO[o][2], f5, f6);
        float4 v;
        v.x = sA[o] * sc; v.y = f1 * sc; v.z = f2 * sc; v.w = f3 * sc;
        *reinterpret_cast<float4*>(op) = v;
        v.x = f4 * sc; v.y = f5 * sc; v.z = f6 * sc; v.w = sB[o] * sc;
        *reinterpret_cast<float4*>(op + 4) = v;
    }
}

extern "C" void kernel_launch(void* const* d_in, const int* in_sizes, int n_in,
                              void* d_out, int out_size) {
    const float* x = (const float*)d_in[0];
    const float* y = (const float*)d_in[1];
    float* out = (float*)d_out;
    (void)in_sizes; (void)n_in; (void)out_size;

    cudaFuncSetAttribute(corr_kernel,
                         cudaFuncAttributeMaxDynamicSharedMemorySize,
                         2 * BUFBYTES);

    dim3 grid(NH / TI, NB);   // (16, 16) = 256 blocks
    corr_kernel<<<grid, NTHREADS, 2 * BUFBYTES>>>(x, y, out);
}